// round 13
// baseline (speedup 1.0000x reference)
#include <cuda_runtime.h>
#include <cuda_fp16.h>
#include <cstdint>

// ============================================================================
// GCN layer: out = relu(diag(d) A diag(d) X W + b), d = rsqrt(rowsum(A))
// R10: split-K reduction fused into GEMM (atomic-counter, last CTA reduces,
//      fixed split order for determinism); KSPLIT=8 for wave balance.
//   k1: d = rsqrt(rowsum A); A_h = f16(A)
//   k2: Zt_h[n,k] = f16( d_k * (X@W)[k,n] )
//   k3: part[s] = A_h @ Zt_h^T ; last CTA per M-tile: out = relu(d*Σp + b)
// ============================================================================

#define NROWS 8192
#define FDIM  128
#define ODIM  128
#define KSPLIT 8

__device__ __align__(128) float  g_d[NROWS];
__device__ __align__(128) __half g_Ah[(size_t)NROWS * NROWS];            // f16(A)
__device__ __align__(128) __half g_Zth[ODIM * NROWS];                    // [n][k] f16
__device__ __align__(128) float  g_part[KSPLIT * (size_t)NROWS * ODIM];  // partials
__device__ int g_cnt[NROWS / 128];                                       // zero-init

// ---------------------------------------------------------------------------
__device__ __forceinline__ uint32_t smem_u32(const void* p) {
    uint32_t a;
    asm("{ .reg .u64 t; cvta.to.shared.u64 t, %1; cvt.u32.u64 %0, t; }"
        : "=r"(a) : "l"(p));
    return a;
}

#define CPA16(dst, src) \
    asm volatile("cp.async.cg.shared.global [%0], [%1], 16;" :: "r"(dst), "l"(src) : "memory")
#define CPA_COMMIT() asm volatile("cp.async.commit_group;" ::: "memory")
#define CPA_WAIT(n)  asm volatile("cp.async.wait_group %0;" :: "n"(n) : "memory")

__device__ __forceinline__ void mma_f16(float* c, const uint32_t* a,
                                        uint32_t b0, uint32_t b1) {
    asm volatile(
        "mma.sync.aligned.m16n8k16.row.col.f32.f16.f16.f32 "
        "{%0,%1,%2,%3}, {%4,%5,%6,%7}, {%8,%9}, {%0,%1,%2,%3};"
        : "+f"(c[0]), "+f"(c[1]), "+f"(c[2]), "+f"(c[3])
        : "r"(a[0]), "r"(a[1]), "r"(a[2]), "r"(a[3]), "r"(b0), "r"(b1));
}

__device__ __forceinline__ void ldsm_x4(uint32_t* d, uint32_t addr) {
    asm volatile("ldmatrix.sync.aligned.m8n8.x4.shared.b16 {%0,%1,%2,%3}, [%4];"
        : "=r"(d[0]), "=r"(d[1]), "=r"(d[2]), "=r"(d[3]) : "r"(addr));
}

// ---------------------------------------------------------------------------
// Kernel 1: d[r] = rsqrt(sum_k A[r,k]); g_Ah = f16(A)
// ---------------------------------------------------------------------------
__global__ __launch_bounds__(256) void rowsum_kernel(const float* __restrict__ A) {
    int row = blockIdx.x;
    const float4* p = reinterpret_cast<const float4*>(A + (size_t)row * NROWS);
    uint2* dst = reinterpret_cast<uint2*>(g_Ah + (size_t)row * NROWS);
    float s = 0.f;
#pragma unroll
    for (int i = 0; i < 8; ++i) {
        int idx = threadIdx.x + i * 256;
        float4 v = p[idx];
        s += (v.x + v.y) + (v.z + v.w);
        __half2 h0 = __floats2half2_rn(v.x, v.y);
        __half2 h1 = __floats2half2_rn(v.z, v.w);
        uint2 u;
        u.x = *reinterpret_cast<uint32_t*>(&h0);
        u.y = *reinterpret_cast<uint32_t*>(&h1);
        dst[idx] = u;
    }
#pragma unroll
    for (int o = 16; o; o >>= 1) s += __shfl_xor_sync(0xffffffffu, s, o);
    __shared__ float ws[8];
    if ((threadIdx.x & 31) == 0) ws[threadIdx.x >> 5] = s;
    __syncthreads();
    if (threadIdx.x < 8) {
        float t = ws[threadIdx.x];
        t += __shfl_xor_sync(0xffu, t, 4);
        t += __shfl_xor_sync(0xffu, t, 2);
        t += __shfl_xor_sync(0xffu, t, 1);
        if (threadIdx.x == 0) g_d[row] = rsqrtf(t);
    }
}

// ---------------------------------------------------------------------------
// Kernel 2: Zt_h[n,k] = f16_rn( d[k] * sum_f X[k,f] W[f,n] )
// ---------------------------------------------------------------------------
__global__ __launch_bounds__(256) void xw_kernel(const float* __restrict__ X,
                                                 const float* __restrict__ W) {
    __shared__ float Ws[128 * 64];
    __shared__ float Xs[16 * 128];
    int tid = threadIdx.x;
    int n0 = blockIdx.y * 64;
    int k0 = blockIdx.x * 16;
    for (int i = tid; i < 128 * 64; i += 256) {
        int f = i >> 6, nl = i & 63;
        Ws[i] = W[f * ODIM + n0 + nl];
    }
    for (int i = tid; i < 16 * 128; i += 256)
        Xs[i] = X[(size_t)(k0 + (i >> 7)) * FDIM + (i & 127)];
    __syncthreads();

    int nl = tid & 63, ks = tid >> 6;
    for (int kk = ks; kk < 16; kk += 4) {
        float acc = 0.f;
#pragma unroll 8
        for (int f = 0; f < 128; ++f) acc += Xs[kk * 128 + f] * Ws[f * 64 + nl];
        int k = k0 + kk;
        g_Zth[(size_t)(n0 + nl) * NROWS + k] = __float2half_rn(g_d[k] * acc);
    }
}

// ---------------------------------------------------------------------------
// Kernel 3: f16 GEMM + fused split-K reduction. grid (64,8), 256 thr.
// CTA 128x128, KT=64, RING=3, 2 CTAs/SM. ldmatrix.x4 fragments, 144B rows.
// ---------------------------------------------------------------------------
static constexpr int KT       = 64;
static constexpr int KC       = NROWS / KSPLIT;  // 1024 per K-split
static constexpr int NKT      = KC / KT;         // 16
static constexpr int ROW_B    = 144;             // 128B payload + 16B pad
static constexpr int TILE_B   = 128 * ROW_B;     // 18432 B
static constexpr int RING     = 3;
static constexpr int DYN_SMEM = 2 * RING * TILE_B;  // 110592 B -> 2 CTAs/SM

__device__ __forceinline__ void ld_tile(uint32_t Au, uint32_t Bu, int slot,
                                        int t, int m0, int kbase, int tid) {
    int k0 = kbase + t * KT;
    uint32_t Ad = Au + slot * TILE_B;
    uint32_t Bd = Bu + slot * TILE_B;
#pragma unroll
    for (int rep = 0; rep < 8; ++rep) {
        int c   = tid + rep * 256;        // 0..2047
        int isB = c >> 10;
        int rc  = c & 1023;
        int row = rc >> 3, seg = rc & 7;
        const __half* src = isB
            ? (g_Zth + (size_t)row * NROWS + k0 + seg * 8)
            : (g_Ah + (size_t)(m0 + row) * NROWS + k0 + seg * 8);
        CPA16((isB ? Bd : Ad) + (uint32_t)(row * ROW_B + seg * 16), src);
    }
}

__global__ __launch_bounds__(256, 2) void gemm_kernel(const float* __restrict__ bias,
                                                      float* __restrict__ out) {
    extern __shared__ __align__(16) char sm[];
    uint32_t Au = smem_u32(sm);
    uint32_t Bu = Au + RING * TILE_B;

    int tid = threadIdx.x, wid = tid >> 5, lane = tid & 31;
    int m0 = blockIdx.x * 128;
    int kbase = blockIdx.y * KC;
    int mw = (wid >> 2) * 64, nw = (wid & 3) * 32;
    int r = lane >> 2, q = lane & 3;

    // ldmatrix per-lane address offsets (within a tile)
    int mi1 = (lane >> 3) & 1, mi2 = lane >> 4, rr = lane & 7;
    uint32_t aoff = (uint32_t)((mw + mi1 * 8 + rr) * ROW_B + mi2 * 16);
    uint32_t boff = (uint32_t)((nw + mi2 * 8 + rr) * ROW_B + mi1 * 16);

    float acc[4][4][4];
#pragma unroll
    for (int i = 0; i < 4; ++i)
#pragma unroll
        for (int j = 0; j < 4; ++j)
#pragma unroll
            for (int v = 0; v < 4; ++v) acc[i][j][v] = 0.f;

    // prologue: tiles 0..RING-2 in flight
#pragma unroll
    for (int s = 0; s < RING - 1; ++s) {
        ld_tile(Au, Bu, s, s, m0, kbase, tid);
        CPA_COMMIT();
    }
    CPA_WAIT(RING - 2);      // tile 0 complete
    __syncthreads();

    uint32_t fa[2][4][4], fb[2][2][4];

    for (int t = 0; t < NKT; ++t) {
        if (t + RING - 1 < NKT)
            ld_tile(Au, Bu, (t + RING - 1) % RING, t + RING - 1, m0, kbase, tid);
        CPA_COMMIT();

        uint32_t At = Au + (t % RING) * TILE_B;
        uint32_t Bt = Bu + (t % RING) * TILE_B;

        // preload ks=0 fragments
#pragma unroll
        for (int i = 0; i < 4; ++i)
            ldsm_x4(fa[0][i], At + aoff + (uint32_t)(i * 16 * ROW_B));
        ldsm_x4(fb[0][0], Bt + boff);
        ldsm_x4(fb[0][1], Bt + boff + (uint32_t)(16 * ROW_B));

#pragma unroll
        for (int ks = 0; ks < 4; ++ks) {
            int cur = ks & 1;
            if (ks < 3) {
                uint32_t ko = (uint32_t)((ks + 1) * 32);
#pragma unroll
                for (int i = 0; i < 4; ++i)
                    ldsm_x4(fa[cur ^ 1][i], At + aoff + ko + (uint32_t)(i * 16 * ROW_B));
                ldsm_x4(fb[cur ^ 1][0], Bt + boff + ko);
                ldsm_x4(fb[cur ^ 1][1], Bt + boff + ko + (uint32_t)(16 * ROW_B));
            }
#pragma unroll
            for (int i = 0; i < 4; ++i) {
                mma_f16(acc[i][0], fa[cur][i], fb[cur][0][0], fb[cur][0][1]);
                mma_f16(acc[i][1], fa[cur][i], fb[cur][0][2], fb[cur][0][3]);
                mma_f16(acc[i][2], fa[cur][i], fb[cur][1][0], fb[cur][1][1]);
                mma_f16(acc[i][3], fa[cur][i], fb[cur][1][2], fb[cur][1][3]);
            }
        }

        CPA_WAIT(RING - 2);  // next tile (t+1) complete
        __syncthreads();
    }

    // write K-split partial
    float* P = g_part + (size_t)blockIdx.y * NROWS * ODIM;
#pragma unroll
    for (int i = 0; i < 4; ++i) {
        int row0 = m0 + mw + i * 16 + r;
#pragma unroll
        for (int j = 0; j < 4; ++j) {
            int col = nw + j * 8 + 2 * q;
            *reinterpret_cast<float2*>(&P[(size_t)row0 * ODIM + col]) =
                make_float2(acc[i][j][0], acc[i][j][1]);
            *reinterpret_cast<float2*>(&P[(size_t)(row0 + 8) * ODIM + col]) =
                make_float2(acc[i][j][2], acc[i][j][3]);
        }
    }

    // ---- fused split-K reduction: last CTA for this M-tile reduces ----
    __threadfence();
    __syncthreads();
    __shared__ int s_last;
    if (tid == 0)
        s_last = (atomicAdd(&g_cnt[blockIdx.x], 1) == KSPLIT - 1);
    __syncthreads();
    if (!s_last) return;
    __threadfence();                       // acquire: see all partials
    if (tid == 0) g_cnt[blockIdx.x] = 0;   // reset for next call

    const float4* P4 = reinterpret_cast<const float4*>(g_part);
    const size_t QT4 = (size_t)NROWS * ODIM / 4;   // float4 per split
    float4* O4 = reinterpret_cast<float4*>(out);
    size_t base4 = (size_t)m0 * 32;                // float4 base of this M-tile
#pragma unroll 4
    for (int u = 0; u < 16; ++u) {
        int i = u * 256 + tid;                     // 0..4095 within tile
        float4 s0 = P4[base4 + i];
#pragma unroll
        for (int s = 1; s < KSPLIT; ++s) {
            float4 p = P4[s * QT4 + base4 + i];
            s0.x += p.x; s0.y += p.y; s0.z += p.z; s0.w += p.w;
        }
        int ml = i >> 5;
        int c = (i & 31) * 4;
        float4 bb = *reinterpret_cast<const float4*>(bias + c);
        float dv = g_d[m0 + ml];
        float4 o;
        o.x = fmaxf(fmaf(dv, s0.x, bb.x), 0.f);
        o.y = fmaxf(fmaf(dv, s0.y, bb.y), 0.f);
        o.z = fmaxf(fmaf(dv, s0.z, bb.z), 0.f);
        o.w = fmaxf(fmaf(dv, s0.w, bb.w), 0.f);
        O4[base4 + i] = o;
    }
}

// ---------------------------------------------------------------------------
extern "C" void kernel_launch(void* const* d_in, const int* in_sizes, int n_in,
                              void* d_out, int out_size) {
    const float* A = (const float*)d_in[0];
    const float* X = (const float*)d_in[1];
    const float* W = (const float*)d_in[2];
    const float* b = (const float*)d_in[3];
    float* out = (float*)d_out;
    (void)in_sizes; (void)n_in; (void)out_size;

    rowsum_kernel<<<NROWS, 256>>>(A);
    dim3 g2(NROWS / 16, 2);
    xw_kernel<<<g2, 256>>>(X, W);
    cudaFuncSetAttribute(gemm_kernel,
                         cudaFuncAttributeMaxDynamicSharedMemorySize, DYN_SMEM);
    dim3 g3(NROWS / 128, KSPLIT);
    gemm_kernel<<<g3, 256, DYN_SMEM>>>(b, out);
}

// round 16
// speedup vs baseline: 1.0540x; 1.0540x over previous
#include <cuda_runtime.h>
#include <cuda_fp16.h>
#include <cstdint>

// ============================================================================
// GCN layer: out = relu(diag(d) A diag(d) X W + b), d = rsqrt(rowsum(A))
// R13: A_h precompute eliminated. GEMM reads f32 A, converts to f16 in regs
//      (LDS.64 + cvt.rn.f16x2). rowsum is a pure 256MB read. KSPLIT=4,
//      separate combine (R10 fused reduction reverted).
//   k1: d = rsqrt(rowsum A)
//   k2: Zt_h[n,k] = f16( d_k * (X@W)[k,n] )
//   k3: part[s] = f16(A) @ Zt_h^T  (HMMA m16n8k16, K-split=4)
//   k4: out = relu(d_m * sum_s p_s + b)
// ============================================================================

#define NROWS 8192
#define FDIM  128
#define ODIM  128
#define KSPLIT 4

__device__ __align__(128) float  g_d[NROWS];
__device__ __align__(128) __half g_Zth[ODIM * NROWS];                    // [n][k] f16
__device__ __align__(128) float  g_part[KSPLIT * (size_t)NROWS * ODIM];  // partials

// ---------------------------------------------------------------------------
__device__ __forceinline__ uint32_t smem_u32(const void* p) {
    uint32_t a;
    asm("{ .reg .u64 t; cvta.to.shared.u64 t, %1; cvt.u32.u64 %0, t; }"
        : "=r"(a) : "l"(p));
    return a;
}

#define CPA16(dst, src) \
    asm volatile("cp.async.cg.shared.global [%0], [%1], 16;" :: "r"(dst), "l"(src) : "memory")
#define CPA_COMMIT() asm volatile("cp.async.commit_group;" ::: "memory")
#define CPA_WAIT(n)  asm volatile("cp.async.wait_group %0;" :: "n"(n) : "memory")

__device__ __forceinline__ void mma_f16(float* c, const uint32_t* a,
                                        uint32_t b0, uint32_t b1) {
    asm volatile(
        "mma.sync.aligned.m16n8k16.row.col.f32.f16.f16.f32 "
        "{%0,%1,%2,%3}, {%4,%5,%6,%7}, {%8,%9}, {%0,%1,%2,%3};"
        : "+f"(c[0]), "+f"(c[1]), "+f"(c[2]), "+f"(c[3])
        : "r"(a[0]), "r"(a[1]), "r"(a[2]), "r"(a[3]), "r"(b0), "r"(b1));
}

__device__ __forceinline__ void ldsm_x4(uint32_t* d, uint32_t addr) {
    asm volatile("ldmatrix.sync.aligned.m8n8.x4.shared.b16 {%0,%1,%2,%3}, [%4];"
        : "=r"(d[0]), "=r"(d[1]), "=r"(d[2]), "=r"(d[3]) : "r"(addr));
}

// LDS.64 of 2 consecutive f32, convert to packed f16x2 (lo = first element)
__device__ __forceinline__ uint32_t lds2_cvt(uint32_t addr) {
    float x, y;
    asm volatile("ld.shared.v2.f32 {%0,%1}, [%2];" : "=f"(x), "=f"(y) : "r"(addr));
    uint32_t d;
    asm("cvt.rn.f16x2.f32 %0, %1, %2;" : "=r"(d) : "f"(y), "f"(x));
    return d;
}

// ---------------------------------------------------------------------------
// Kernel 1: d[r] = rsqrt(sum_k A[r,k])  (pure read, BW floor)
// ---------------------------------------------------------------------------
__global__ __launch_bounds__(256) void rowsum_kernel(const float* __restrict__ A) {
    int row = blockIdx.x;
    const float4* p = reinterpret_cast<const float4*>(A + (size_t)row * NROWS);
    float s = 0.f;
#pragma unroll
    for (int i = 0; i < 8; ++i) {
        float4 v = p[threadIdx.x + i * 256];
        s += (v.x + v.y) + (v.z + v.w);
    }
#pragma unroll
    for (int o = 16; o; o >>= 1) s += __shfl_xor_sync(0xffffffffu, s, o);
    __shared__ float ws[8];
    if ((threadIdx.x & 31) == 0) ws[threadIdx.x >> 5] = s;
    __syncthreads();
    if (threadIdx.x < 8) {
        float t = ws[threadIdx.x];
        t += __shfl_xor_sync(0xffu, t, 4);
        t += __shfl_xor_sync(0xffu, t, 2);
        t += __shfl_xor_sync(0xffu, t, 1);
        if (threadIdx.x == 0) g_d[row] = rsqrtf(t);
    }
}

// ---------------------------------------------------------------------------
// Kernel 2: Zt_h[n,k] = f16_rn( d[k] * sum_f X[k,f] W[f,n] )
// ---------------------------------------------------------------------------
__global__ __launch_bounds__(256) void xw_kernel(const float* __restrict__ X,
                                                 const float* __restrict__ W) {
    __shared__ float Ws[128 * 64];
    __shared__ float Xs[16 * 128];
    int tid = threadIdx.x;
    int n0 = blockIdx.y * 64;
    int k0 = blockIdx.x * 16;
    for (int i = tid; i < 128 * 64; i += 256) {
        int f = i >> 6, nl = i & 63;
        Ws[i] = W[f * ODIM + n0 + nl];
    }
    for (int i = tid; i < 16 * 128; i += 256)
        Xs[i] = X[(size_t)(k0 + (i >> 7)) * FDIM + (i & 127)];
    __syncthreads();

    int nl = tid & 63, ks = tid >> 6;
    for (int kk = ks; kk < 16; kk += 4) {
        float acc = 0.f;
#pragma unroll 8
        for (int f = 0; f < 128; ++f) acc += Xs[kk * 128 + f] * Ws[f * 64 + nl];
        int k = k0 + kk;
        g_Zth[(size_t)(n0 + nl) * NROWS + k] = __float2half_rn(g_d[k] * acc);
    }
}

// ---------------------------------------------------------------------------
// Kernel 3: GEMM, A staged f32 (inline cvt), B staged f16. grid (64,4),
// 256 thr (8 warps, 64x32 warp tile). CTA 128x128, KT=32, RING=3, 2 CTAs/SM.
// A rows 160B (LDS.64 conflict-free: (8r+2q)%32 covers banks per phase).
// B rows 80B (ldsm conflict-free: odd 16B stride).
// ---------------------------------------------------------------------------
static constexpr int KT       = 32;
static constexpr int KC       = NROWS / KSPLIT;  // 2048 per K-split
static constexpr int NKT      = KC / KT;         // 64
static constexpr int ROW_A    = 160;             // 128B f32 payload + 32B pad
static constexpr int ROW_Bf   = 80;              // 64B f16 payload + 16B pad
static constexpr int TILE_A   = 128 * ROW_A;     // 20480
static constexpr int TILE_Bf  = 128 * ROW_Bf;    // 10240
static constexpr int RING     = 3;
static constexpr int DYN_SMEM = RING * (TILE_A + TILE_Bf);  // 92160 -> 2 CTAs/SM

__device__ __forceinline__ void ld_tile(uint32_t Au, uint32_t Bu, int slot,
                                        int t, const float* __restrict__ A,
                                        int m0, int kbase, int tid) {
    int k0 = kbase + t * KT;
    uint32_t Ad = Au + slot * TILE_A;
    uint32_t Bd = Bu + slot * TILE_Bf;
    // A: 128 rows x 128B f32 payload = 1024 chunks of 16B
#pragma unroll
    for (int rep = 0; rep < 4; ++rep) {
        int c = tid + rep * 256;
        int row = c >> 3, seg = c & 7;
        CPA16(Ad + (uint32_t)(row * ROW_A + seg * 16),
              A + (size_t)(m0 + row) * NROWS + k0 + seg * 4);
    }
    // B: 128 rows x 64B f16 payload = 512 chunks of 16B
#pragma unroll
    for (int rep = 0; rep < 2; ++rep) {
        int c = tid + rep * 256;
        int row = c >> 2, seg = c & 3;
        CPA16(Bd + (uint32_t)(row * ROW_Bf + seg * 16),
              g_Zth + (size_t)row * NROWS + k0 + seg * 8);
    }
}

__device__ __forceinline__ void ld_frag_a(uint32_t At, int mw, int r, int q,
                                          int ks, uint32_t a[4][4]) {
    uint32_t base = At + (uint32_t)(ks * 64 + q * 8);
#pragma unroll
    for (int i = 0; i < 4; ++i) {
        uint32_t p0 = base + (uint32_t)((mw + i * 16 + r) * ROW_A);
        uint32_t p1 = p0 + 8u * ROW_A;
        a[i][0] = lds2_cvt(p0);
        a[i][1] = lds2_cvt(p1);
        a[i][2] = lds2_cvt(p0 + 32u);
        a[i][3] = lds2_cvt(p1 + 32u);
    }
}

__global__ __launch_bounds__(256, 2) void gemm_kernel(const float* __restrict__ A) {
    extern __shared__ __align__(16) char sm[];
    uint32_t Au = smem_u32(sm);
    uint32_t Bu = Au + RING * TILE_A;

    int tid = threadIdx.x, wid = tid >> 5, lane = tid & 31;
    int m0 = blockIdx.x * 128;
    int kbase = blockIdx.y * KC;
    int mw = (wid >> 2) * 64, nw = (wid & 3) * 32;
    int r = lane >> 2, q = lane & 3;

    // ldmatrix per-lane offset for B (same mapping as R9, ROW_Bf rows)
    int mi1 = (lane >> 3) & 1, mi2 = lane >> 4, rr = lane & 7;
    uint32_t boff = (uint32_t)((nw + mi2 * 8 + rr) * ROW_Bf + mi1 * 16);

    float acc[4][4][4];
#pragma unroll
    for (int i = 0; i < 4; ++i)
#pragma unroll
        for (int j = 0; j < 4; ++j)
#pragma unroll
            for (int v = 0; v < 4; ++v) acc[i][j][v] = 0.f;

    // prologue: tiles 0..RING-2 in flight
#pragma unroll
    for (int s = 0; s < RING - 1; ++s) {
        ld_tile(Au, Bu, s, s, A, m0, kbase, tid);
        CPA_COMMIT();
    }
    CPA_WAIT(RING - 2);      // tile 0 complete
    __syncthreads();

    uint32_t fa[2][4][4], fb[2][2][4];

    for (int t = 0; t < NKT; ++t) {
        if (t + RING - 1 < NKT)
            ld_tile(Au, Bu, (t + RING - 1) % RING, t + RING - 1, A, m0, kbase, tid);
        CPA_COMMIT();

        uint32_t At = Au + (t % RING) * TILE_A;
        uint32_t Bt = Bu + (t % RING) * TILE_Bf;

        // preload ks=0 fragments
        ld_frag_a(At, mw, r, q, 0, fa[0]);
        ldsm_x4(fb[0][0], Bt + boff);
        ldsm_x4(fb[0][1], Bt + boff + (uint32_t)(16 * ROW_Bf));

#pragma unroll
        for (int ks = 0; ks < 2; ++ks) {
            int cur = ks & 1;
            if (ks == 0) {
                ld_frag_a(At, mw, r, q, 1, fa[1]);
                ldsm_x4(fb[1][0], Bt + boff + 32u);
                ldsm_x4(fb[1][1], Bt + boff + 32u + (uint32_t)(16 * ROW_Bf));
            }
#pragma unroll
            for (int i = 0; i < 4; ++i) {
                mma_f16(acc[i][0], fa[cur][i], fb[cur][0][0], fb[cur][0][1]);
                mma_f16(acc[i][1], fa[cur][i], fb[cur][0][2], fb[cur][0][3]);
                mma_f16(acc[i][2], fa[cur][i], fb[cur][1][0], fb[cur][1][1]);
                mma_f16(acc[i][3], fa[cur][i], fb[cur][1][2], fb[cur][1][3]);
            }
        }

        CPA_WAIT(RING - 2);  // next tile (t+1) complete
        __syncthreads();
    }

    // write K-split partials
    float* P = g_part + (size_t)blockIdx.y * NROWS * ODIM;
#pragma unroll
    for (int i = 0; i < 4; ++i) {
        int row0 = m0 + mw + i * 16 + r;
#pragma unroll
        for (int j = 0; j < 4; ++j) {
            int col = nw + j * 8 + 2 * q;
            *reinterpret_cast<float2*>(&P[(size_t)row0 * ODIM + col]) =
                make_float2(acc[i][j][0], acc[i][j][1]);
            *reinterpret_cast<float2*>(&P[(size_t)(row0 + 8) * ODIM + col]) =
                make_float2(acc[i][j][2], acc[i][j][3]);
        }
    }
}

// ---------------------------------------------------------------------------
// Kernel 4: out = relu(d_m * sum_s p_s + b_n). grid 1024 (high occupancy).
// ---------------------------------------------------------------------------
__global__ __launch_bounds__(256) void combine_kernel(const float* __restrict__ bias,
                                                      float* __restrict__ out) {
    const float4* P = reinterpret_cast<const float4*>(g_part);
    const size_t QT = (size_t)NROWS * ODIM / 4;
    float4* O = reinterpret_cast<float4*>(out);
    int i = blockIdx.x * 256 + threadIdx.x;
    float4 p0 = P[i];
    float4 p1 = P[i + QT];
    float4 p2 = P[i + 2 * QT];
    float4 p3 = P[i + 3 * QT];
    float sx = (p0.x + p1.x) + (p2.x + p3.x);
    float sy = (p0.y + p1.y) + (p2.y + p3.y);
    float sz = (p0.z + p1.z) + (p2.z + p3.z);
    float sw = (p0.w + p1.w) + (p2.w + p3.w);
    int m = i >> 5;
    int c = (i & 31) * 4;
    float4 bb = *reinterpret_cast<const float4*>(bias + c);
    float dv = g_d[m];
    float4 o;
    o.x = fmaxf(fmaf(dv, sx, bb.x), 0.f);
    o.y = fmaxf(fmaf(dv, sy, bb.y), 0.f);
    o.z = fmaxf(fmaf(dv, sz, bb.z), 0.f);
    o.w = fmaxf(fmaf(dv, sw, bb.w), 0.f);
    O[i] = o;
}

// ---------------------------------------------------------------------------
extern "C" void kernel_launch(void* const* d_in, const int* in_sizes, int n_in,
                              void* d_out, int out_size) {
    const float* A = (const float*)d_in[0];
    const float* X = (const float*)d_in[1];
    const float* W = (const float*)d_in[2];
    const float* b = (const float*)d_in[3];
    float* out = (float*)d_out;
    (void)in_sizes; (void)n_in; (void)out_size;

    rowsum_kernel<<<NROWS, 256>>>(A);
    dim3 g2(NROWS / 16, 2);
    xw_kernel<<<g2, 256>>>(X, W);
    cudaFuncSetAttribute(gemm_kernel,
                         cudaFuncAttributeMaxDynamicSharedMemorySize, DYN_SMEM);
    dim3 g3(NROWS / 128, KSPLIT);
    gemm_kernel<<<g3, 256, DYN_SMEM>>>(A);
    combine_kernel<<<NROWS * ODIM / 4 / 256, 256>>>(b, out);
}